// round 5
// baseline (speedup 1.0000x reference)
#include <cuda_runtime.h>
#include <cuda_fp16.h>
#include <cstdint>

#define DEVINL __device__ __forceinline__

// ---------------- problem sizes ----------------
constexpr int Bb = 32, Ss = 2048, Hh = 1024;
constexpr int M_TOTAL = Bb * Ss;          // 65536
constexpr int BM = 128, BN = 256, BK = 32;   // K-step = 32 elements
constexpr int NSTEPS = Hh / BK;           // 32
constexpr int NT = Hh / BN;               // 4 N-tiles
constexpr int LDH = 40;                   // padded smem row stride in halves (80B)
constexpr int PIPE = 4;                   // cp.async stages
constexpr int NTHREADS = 512;             // 16 warps

// ---------------- scratch (no allocs allowed) ----------------
__device__ float  g_ws[Bb * Hh];          // W_s @ dec
__device__ __half g_wh_h[Hh * Hh];        // fp16 W_h
__device__ __half g_enc_h[(size_t)M_TOTAL * Hh];  // fp16 encoder (128 MB)
__device__ float  g_part[NT][M_TOTAL];    // partial scores per N-tile

struct SmemK1 {
    __half A[PIPE][BM][LDH];   // 4*128*80B = 40,960 B
    __half B[PIPE][BN][LDH];   // 4*256*80B = 81,920 B
    float ws[BN];
    float v[BN];
    float rowsum[BM];
};

// ---------------- helpers ----------------
DEVINL uint32_t smem_u32(const void* p) {
    uint32_t a;
    asm("{ .reg .u64 t; cvta.to.shared.u64 t, %1; cvt.u32.u64 %0, t; }" : "=r"(a) : "l"(p));
    return a;
}
DEVINL float tanh_fast(float x) {
    float r;
    asm("tanh.approx.f32 %0, %1;" : "=f"(r) : "f"(x));
    return r;
}
DEVINL void cp_async16(uint32_t dst, const void* src) {
    asm volatile("cp.async.cg.shared.global [%0], [%1], 16;" :: "r"(dst), "l"(src));
}
DEVINL void cp_commit() { asm volatile("cp.async.commit_group;"); }
DEVINL void cp_wait3()  { asm volatile("cp.async.wait_group 3;"); }

DEVINL void ldmatrix_x4(uint32_t r[4], uint32_t addr) {
    asm volatile("ldmatrix.sync.aligned.m8n8.x4.shared.b16 {%0,%1,%2,%3}, [%4];"
                 : "=r"(r[0]), "=r"(r[1]), "=r"(r[2]), "=r"(r[3]) : "r"(addr));
}
DEVINL void mma_f16(float c[4], const uint32_t a[4], const uint32_t b[2]) {
    asm volatile(
        "mma.sync.aligned.m16n8k16.row.col.f32.f16.f16.f32 "
        "{%0,%1,%2,%3}, {%4,%5,%6,%7}, {%8,%9}, {%0,%1,%2,%3};"
        : "+f"(c[0]), "+f"(c[1]), "+f"(c[2]), "+f"(c[3])
        : "r"(a[0]), "r"(a[1]), "r"(a[2]), "r"(a[3]), "r"(b[0]), "r"(b[1]));
}
DEVINL uint32_t pack_h2(float lo, float hi) {
    __half2 h = __floats2half2_rn(lo, hi);
    return *reinterpret_cast<uint32_t*>(&h);
}

// ================= K0a: W_h -> fp16 =================
__global__ void wh_to_half_kernel(const float* __restrict__ Wh) {
    int i = (blockIdx.x * 256 + threadIdx.x) * 4;
    float4 v = *reinterpret_cast<const float4*>(Wh + i);
    uint2 u;
    u.x = pack_h2(v.x, v.y);
    u.y = pack_h2(v.z, v.w);
    *reinterpret_cast<uint2*>(g_wh_h + i) = u;
}

// ================= K0c: enc -> fp16 (8 elements/thread) =================
__global__ void enc_to_half_kernel(const float* __restrict__ enc) {
    size_t i = ((size_t)blockIdx.x * 256 + threadIdx.x) * 8;
    float4 v0 = *reinterpret_cast<const float4*>(enc + i);
    float4 v1 = *reinterpret_cast<const float4*>(enc + i + 4);
    uint4 u;
    u.x = pack_h2(v0.x, v0.y); u.y = pack_h2(v0.z, v0.w);
    u.z = pack_h2(v1.x, v1.y); u.w = pack_h2(v1.z, v1.w);
    *reinterpret_cast<uint4*>(g_enc_h + i) = u;
}

// ================= K0b: ws[b,o] = dec[b,:] . W_s[o,:] (fp32 exact) =================
__global__ void ws_kernel(const float* __restrict__ dec, const float* __restrict__ Wsm) {
    int idx = blockIdx.x * 8 + (threadIdx.x >> 5);
    int lid = threadIdx.x & 31;
    int b = idx >> 10, o = idx & 1023;
    const float* dr = dec + (size_t)b * Hh;
    const float* wr = Wsm + (size_t)o * Hh;
    float acc = 0.f;
#pragma unroll
    for (int i = 0; i < 8; i++) {
        int k = (i * 32 + lid) * 4;
        float4 d4 = *reinterpret_cast<const float4*>(dr + k);
        float4 w4 = *reinterpret_cast<const float4*>(wr + k);
        acc += d4.x * w4.x + d4.y * w4.y + d4.z * w4.z + d4.w * w4.w;
    }
#pragma unroll
    for (int off = 16; off; off >>= 1) acc += __shfl_xor_sync(0xffffffffu, acc, off);
    if (lid == 0) g_ws[idx] = acc;
}

// ================= K1: fused fp16 GEMM + tanh + v-dot -> partial scores =================
// 512 threads, 16 warps in a 4(m) x 4(n) grid; warp tile 32(M) x 64(N).
__global__ __launch_bounds__(NTHREADS, 1) void attn_scores_kernel(const float* __restrict__ vvec) {
    extern __shared__ char smraw[];
    SmemK1& sm = *reinterpret_cast<SmemK1*>(smraw);

    const int tid = threadIdx.x, wid = tid >> 5, lane = tid & 31;
    const int g = lane >> 2, t = lane & 3;
    const int wm = (wid >> 2) * 32;       // 4 m-groups of 32 rows
    const int wn = (wid & 3) * 64;        // 4 n-groups of 64 cols
    const int m_base = blockIdx.y * BM;
    const int n_base = blockIdx.x * BN;
    const int b = m_base >> 11;

    for (int i = tid; i < BN; i += NTHREADS) {
        sm.ws[i] = g_ws[b * Hh + n_base + i];
        sm.v[i]  = vvec[n_base + i];
    }
    if (tid < BM) sm.rowsum[tid] = 0.f;

    // cp.async chunk coordinates: 16B chunks, 4 per 64B k-row
    const int rA = tid >> 2, cA = tid & 3;     // A: 128 rows * 4 chunks = 512 = 1/thread
    const __half* srcA = g_enc_h + (size_t)(m_base + rA) * Hh + cA * 8;
    const __half* srcB = g_wh_h  + (size_t)(n_base + rA) * Hh + cA * 8;   // rows rA, rA+128

    auto issue_stage = [&](int stage, int k0) {
        cp_async16(smem_u32(reinterpret_cast<char*>(&sm.A[stage][rA][0]) + cA * 16),
                   srcA + k0);
#pragma unroll
        for (int i = 0; i < 2; i++)
            cp_async16(smem_u32(reinterpret_cast<char*>(&sm.B[stage][rA + i * 128][0]) + cA * 16),
                       srcB + (size_t)(i * 128) * Hh + k0);
        cp_commit();
    };

    float acc[2][8][4];
#pragma unroll
    for (int ma = 0; ma < 2; ma++)
#pragma unroll
        for (int na = 0; na < 8; na++)
#pragma unroll
            for (int r = 0; r < 4; r++) acc[ma][na][r] = 0.f;

    // ldmatrix lane offset
    const int lr = lane & 7, sel = lane >> 3;
    const uint32_t lane_off = (uint32_t)((lr + (sel & 1) * 8) * (LDH * 2) + (sel >> 1) * 16);
    const uint32_t baseA = smem_u32(&sm.A[0][0][0]);
    const uint32_t baseB = smem_u32(&sm.B[0][0][0]);
    constexpr uint32_t A_STRIDE = BM * LDH * 2;   // bytes per stage
    constexpr uint32_t B_STRIDE = BN * LDH * 2;

    // prologue: fill stages 0..2
    issue_stage(0, 0);
    issue_stage(1, BK);
    issue_stage(2, 2 * BK);

#pragma unroll 1
    for (int s = 0; s < NSTEPS; s++) {
        int p = s & (PIPE - 1);
        if (s + 3 < NSTEPS) issue_stage((s + 3) & (PIPE - 1), (s + 3) * BK);
        else                cp_commit();             // empty group keeps count uniform
        cp_wait3();                                  // stage s complete
        __syncthreads();

        uint32_t aw = baseA + p * A_STRIDE + (uint32_t)(wm * (LDH * 2)) + lane_off;
        uint32_t bw = baseB + p * B_STRIDE + (uint32_t)(wn * (LDH * 2)) + lane_off;
#pragma unroll
        for (int ka = 0; ka < 2; ka++) {
            uint32_t af[2][4];
#pragma unroll
            for (int ma = 0; ma < 2; ma++)
                ldmatrix_x4(af[ma], aw + (uint32_t)(ma * 16 * (LDH * 2)) + ka * 32);
            uint32_t bf[8][2];
#pragma unroll
            for (int nb = 0; nb < 4; nb++) {
                uint32_t r[4];
                ldmatrix_x4(r, bw + (uint32_t)(nb * 16 * (LDH * 2)) + ka * 32);
                bf[2 * nb][0] = r[0]; bf[2 * nb + 1][0] = r[1];
                bf[2 * nb][1] = r[2]; bf[2 * nb + 1][1] = r[3];
            }
#pragma unroll
            for (int ma = 0; ma < 2; ma++)
#pragma unroll
                for (int na = 0; na < 8; na++)
                    mma_f16(acc[ma][na], af[ma], bf[na]);
        }
        __syncthreads();   // all reads of stage s done before it is refilled
    }

    // epilogue: tanh(acc + ws)*v, reduce over n
#pragma unroll
    for (int ma = 0; ma < 2; ma++) {
        float r0 = 0.f, r1 = 0.f;
#pragma unroll
        for (int na = 0; na < 8; na++) {
            int nl = wn + na * 8 + 2 * t;
            float w0 = sm.ws[nl], w1 = sm.ws[nl + 1];
            float v0 = sm.v[nl],  v1 = sm.v[nl + 1];
            r0 += tanh_fast(acc[ma][na][0] + w0) * v0 + tanh_fast(acc[ma][na][1] + w1) * v1;
            r1 += tanh_fast(acc[ma][na][2] + w0) * v0 + tanh_fast(acc[ma][na][3] + w1) * v1;
        }
        r0 += __shfl_xor_sync(0xffffffffu, r0, 1);
        r0 += __shfl_xor_sync(0xffffffffu, r0, 2);
        r1 += __shfl_xor_sync(0xffffffffu, r1, 1);
        r1 += __shfl_xor_sync(0xffffffffu, r1, 2);
        if (t == 0) {
            atomicAdd(&sm.rowsum[wm + ma * 16 + g], r0);
            atomicAdd(&sm.rowsum[wm + ma * 16 + g + 8], r1);
        }
    }
    __syncthreads();
    if (tid < BM) g_part[blockIdx.x][m_base + tid] = sm.rowsum[tid];
}

// ================= K2: softmax over S per batch =================
__global__ void softmax_kernel(float* __restrict__ wout) {
    __shared__ float sc[Ss];
    __shared__ float red[256];
    int b = blockIdx.x, tid = threadIdx.x;
    float mx = -1e30f;
    for (int i = tid; i < Ss; i += 256) {
        int idx = b * Ss + i;
        float v = g_part[0][idx] + g_part[1][idx] + g_part[2][idx] + g_part[3][idx];
        sc[i] = v;
        mx = fmaxf(mx, v);
    }
    red[tid] = mx; __syncthreads();
    for (int o = 128; o; o >>= 1) { if (tid < o) red[tid] = fmaxf(red[tid], red[tid + o]); __syncthreads(); }
    mx = red[0]; __syncthreads();
    float sum = 0.f;
    for (int i = tid; i < Ss; i += 256) { float e = __expf(sc[i] - mx); sc[i] = e; sum += e; }
    red[tid] = sum; __syncthreads();
    for (int o = 128; o; o >>= 1) { if (tid < o) red[tid] += red[tid + o]; __syncthreads(); }
    float inv = 1.f / red[0];
    for (int i = tid; i < Ss; i += 256) wout[b * Ss + i] = sc[i] * inv;
}

// ================= K3: context[b,h] = sum_s w[b,s] * enc[b,s,h] (fp16 enc) =================
__global__ void context_kernel(const float* __restrict__ w, float* __restrict__ out) {
    __shared__ float wsh[Ss];
    int b = blockIdx.y;
    int h2 = blockIdx.x * 256 + threadIdx.x;   // half2 column index, 0..511
    for (int i = threadIdx.x; i < Ss; i += 256) wsh[i] = w[b * Ss + i];
    __syncthreads();
    const __half2* e = reinterpret_cast<const __half2*>(g_enc_h) + (size_t)b * Ss * (Hh / 2) + h2;
    float a0 = 0.f, a1 = 0.f, b0 = 0.f, b1 = 0.f;
#pragma unroll 4
    for (int s = 0; s < Ss; s += 2) {
        float2 f0 = __half22float2(e[(size_t)s * (Hh / 2)]);
        float2 f1 = __half22float2(e[(size_t)(s + 1) * (Hh / 2)]);
        a0 += wsh[s] * f0.x;     a1 += wsh[s] * f0.y;
        b0 += wsh[s + 1] * f1.x; b1 += wsh[s + 1] * f1.y;
    }
    out[b * Hh + 2 * h2]     = a0 + b0;
    out[b * Hh + 2 * h2 + 1] = a1 + b1;
}

// ================= launcher =================
extern "C" void kernel_launch(void* const* d_in, const int* in_sizes, int n_in,
                              void* d_out, int out_size) {
    (void)in_sizes; (void)n_in; (void)out_size;
    const float* dec = (const float*)d_in[0];   // [32,1024]
    const float* enc = (const float*)d_in[1];   // [32,2048,1024]
    const float* Wh  = (const float*)d_in[2];   // [1024,1024]
    const float* Wsm = (const float*)d_in[3];   // [1024,1024]
    const float* v   = (const float*)d_in[4];   // [1024]
    float* out  = (float*)d_out;
    float* ctx  = out;                 // [32,1024]
    float* attw = out + Bb * Hh;       // [32,2048]

    cudaFuncSetAttribute(attn_scores_kernel, cudaFuncAttributeMaxDynamicSharedMemorySize,
                         (int)sizeof(SmemK1));

    wh_to_half_kernel<<<Hh * Hh / 1024, 256>>>(Wh);
    enc_to_half_kernel<<<(int)((size_t)M_TOTAL * Hh / 2048), 256>>>(enc);
    ws_kernel<<<Bb * Hh / 8, 256>>>(dec, Wsm);
    attn_scores_kernel<<<dim3(NT, M_TOTAL / BM), NTHREADS, sizeof(SmemK1)>>>(v);
    softmax_kernel<<<Bb, 256>>>(attw);
    context_kernel<<<dim3(Hh / 512, Bb), 256>>>(attw, ctx);
}

// round 6
// speedup vs baseline: 1.1371x; 1.1371x over previous
#include <cuda_runtime.h>
#include <cuda_fp16.h>
#include <cstdint>

#define DEVINL __device__ __forceinline__

// ---------------- problem sizes ----------------
constexpr int Bb = 32, Ss = 2048, Hh = 1024;
constexpr int M_TOTAL = Bb * Ss;          // 65536
constexpr int BM = 128, BN = 256, BK = 64;   // K-step = 64 elements
constexpr int NSTEPS = Hh / BK;           // 16
constexpr int NT = Hh / BN;               // 4 N-tiles
constexpr int LDH = 72;                   // padded smem row stride in halves (144B)
constexpr int PIPE = 3;                   // cp.async stages
constexpr int NTHREADS = 512;             // 16 warps

// ---------------- scratch (no allocs allowed) ----------------
__device__ float  g_ws[Bb * Hh];          // W_s @ dec
__device__ __half g_wh_h[Hh * Hh];        // fp16 W_h
__device__ __half g_enc_h[(size_t)M_TOTAL * Hh];  // fp16 encoder (128 MB)
__device__ float  g_part[NT][M_TOTAL];    // partial scores per N-tile

struct SmemK1 {
    __half A[PIPE][BM][LDH];   // 3*128*144B = 55,296 B
    __half B[PIPE][BN][LDH];   // 3*256*144B = 110,592 B
    float ws[BN];
    float v[BN];
    float rowsum[BM];
};

// ---------------- helpers ----------------
DEVINL uint32_t smem_u32(const void* p) {
    uint32_t a;
    asm("{ .reg .u64 t; cvta.to.shared.u64 t, %1; cvt.u32.u64 %0, t; }" : "=r"(a) : "l"(p));
    return a;
}
DEVINL float tanh_fast(float x) {
    float r;
    asm("tanh.approx.f32 %0, %1;" : "=f"(r) : "f"(x));
    return r;
}
DEVINL void cp_async16(uint32_t dst, const void* src) {
    asm volatile("cp.async.cg.shared.global [%0], [%1], 16;" :: "r"(dst), "l"(src));
}
DEVINL void cp_commit() { asm volatile("cp.async.commit_group;"); }
DEVINL void cp_wait1()  { asm volatile("cp.async.wait_group 1;"); }

DEVINL void ldmatrix_x4(uint32_t r[4], uint32_t addr) {
    asm volatile("ldmatrix.sync.aligned.m8n8.x4.shared.b16 {%0,%1,%2,%3}, [%4];"
                 : "=r"(r[0]), "=r"(r[1]), "=r"(r[2]), "=r"(r[3]) : "r"(addr));
}
DEVINL void mma_f16(float c[4], const uint32_t a[4], const uint32_t b[2]) {
    asm volatile(
        "mma.sync.aligned.m16n8k16.row.col.f32.f16.f16.f32 "
        "{%0,%1,%2,%3}, {%4,%5,%6,%7}, {%8,%9}, {%0,%1,%2,%3};"
        : "+f"(c[0]), "+f"(c[1]), "+f"(c[2]), "+f"(c[3])
        : "r"(a[0]), "r"(a[1]), "r"(a[2]), "r"(a[3]), "r"(b[0]), "r"(b[1]));
}
DEVINL uint32_t pack_h2(float lo, float hi) {
    __half2 h = __floats2half2_rn(lo, hi);
    return *reinterpret_cast<uint32_t*>(&h);
}

// ================= K0a: W_h -> fp16 =================
__global__ void wh_to_half_kernel(const float* __restrict__ Wh) {
    int i = (blockIdx.x * 256 + threadIdx.x) * 4;
    float4 v = *reinterpret_cast<const float4*>(Wh + i);
    uint2 u;
    u.x = pack_h2(v.x, v.y);
    u.y = pack_h2(v.z, v.w);
    *reinterpret_cast<uint2*>(g_wh_h + i) = u;
}

// ================= K0c: enc -> fp16 (8 elements/thread) =================
__global__ void enc_to_half_kernel(const float* __restrict__ enc) {
    size_t i = ((size_t)blockIdx.x * 256 + threadIdx.x) * 8;
    float4 v0 = *reinterpret_cast<const float4*>(enc + i);
    float4 v1 = *reinterpret_cast<const float4*>(enc + i + 4);
    uint4 u;
    u.x = pack_h2(v0.x, v0.y); u.y = pack_h2(v0.z, v0.w);
    u.z = pack_h2(v1.x, v1.y); u.w = pack_h2(v1.z, v1.w);
    *reinterpret_cast<uint4*>(g_enc_h + i) = u;
}

// ================= K0b: ws[b,o] = dec[b,:] . W_s[o,:] (fp32 exact) =================
__global__ void ws_kernel(const float* __restrict__ dec, const float* __restrict__ Wsm) {
    int idx = blockIdx.x * 8 + (threadIdx.x >> 5);
    int lid = threadIdx.x & 31;
    int b = idx >> 10, o = idx & 1023;
    const float* dr = dec + (size_t)b * Hh;
    const float* wr = Wsm + (size_t)o * Hh;
    float acc = 0.f;
#pragma unroll
    for (int i = 0; i < 8; i++) {
        int k = (i * 32 + lid) * 4;
        float4 d4 = *reinterpret_cast<const float4*>(dr + k);
        float4 w4 = *reinterpret_cast<const float4*>(wr + k);
        acc += d4.x * w4.x + d4.y * w4.y + d4.z * w4.z + d4.w * w4.w;
    }
#pragma unroll
    for (int off = 16; off; off >>= 1) acc += __shfl_xor_sync(0xffffffffu, acc, off);
    if (lid == 0) g_ws[idx] = acc;
}

// ================= K1: fused fp16 GEMM + tanh + v-dot -> partial scores =================
// 512 threads, 16 warps in 4(m) x 4(n) grid; warp tile 32(M) x 64(N); BK=64, single sync/step.
__global__ __launch_bounds__(NTHREADS, 1) void attn_scores_kernel(const float* __restrict__ vvec) {
    extern __shared__ char smraw[];
    SmemK1& sm = *reinterpret_cast<SmemK1*>(smraw);

    const int tid = threadIdx.x, wid = tid >> 5, lane = tid & 31;
    const int g = lane >> 2, t = lane & 3;
    const int wm = (wid >> 2) * 32;       // 4 m-groups of 32 rows
    const int wn = (wid & 3) * 64;        // 4 n-groups of 64 cols
    const int m_base = blockIdx.y * BM;
    const int n_base = blockIdx.x * BN;
    const int b = m_base >> 11;

    for (int i = tid; i < BN; i += NTHREADS) {
        sm.ws[i] = g_ws[b * Hh + n_base + i];
        sm.v[i]  = vvec[n_base + i];
    }
    if (tid < BM) sm.rowsum[tid] = 0.f;

    // cp.async chunk coordinates: 16B chunks, 8 per 128B k-row (BK=64 halves)
    const int rA = tid >> 3, cA = tid & 7;     // rows 0..63 (+64), chunk col 0..7
    const __half* srcA = g_enc_h + (size_t)(m_base + rA) * Hh + cA * 8;
    const __half* srcB = g_wh_h  + (size_t)(n_base + rA) * Hh + cA * 8;

    auto issue_stage = [&](int stage, int k0) {
#pragma unroll
        for (int i = 0; i < 2; i++)   // A rows rA, rA+64
            cp_async16(smem_u32(reinterpret_cast<char*>(&sm.A[stage][rA + i * 64][0]) + cA * 16),
                       srcA + (size_t)(i * 64) * Hh + k0);
#pragma unroll
        for (int i = 0; i < 4; i++)   // B rows rA, rA+64, rA+128, rA+192
            cp_async16(smem_u32(reinterpret_cast<char*>(&sm.B[stage][rA + i * 64][0]) + cA * 16),
                       srcB + (size_t)(i * 64) * Hh + k0);
        cp_commit();
    };

    float acc[2][8][4];
#pragma unroll
    for (int ma = 0; ma < 2; ma++)
#pragma unroll
        for (int na = 0; na < 8; na++)
#pragma unroll
            for (int r = 0; r < 4; r++) acc[ma][na][r] = 0.f;

    // ldmatrix lane offset (row stride 144B: 8 rows cover distinct 16B spans mod 128B)
    const int lr = lane & 7, sel = lane >> 3;
    const uint32_t lane_off = (uint32_t)((lr + (sel & 1) * 8) * (LDH * 2) + (sel >> 1) * 16);
    const uint32_t baseA = smem_u32(&sm.A[0][0][0]);
    const uint32_t baseB = smem_u32(&sm.B[0][0][0]);
    constexpr uint32_t A_STRIDE = BM * LDH * 2;   // bytes per stage
    constexpr uint32_t B_STRIDE = BN * LDH * 2;

    // prologue: fill stages 0,1
    issue_stage(0, 0);
    issue_stage(1, BK);

    int p = 0;
#pragma unroll 1
    for (int s = 0; s < NSTEPS; s++) {
        cp_wait1();          // stage s complete (<=1 group in flight)
        __syncthreads();     // visible to all; also: all reads of buffer (s-1) finished

        if (s + 2 < NSTEPS) {
            int nxt = p + 2; if (nxt >= PIPE) nxt -= PIPE;
            issue_stage(nxt, (s + 2) * BK);   // overwrites buffer (s-1): safe after sync
        } else {
            cp_commit();                      // empty group keeps accounting uniform
        }

        uint32_t aw = baseA + p * A_STRIDE + (uint32_t)(wm * (LDH * 2)) + lane_off;
        uint32_t bw = baseB + p * B_STRIDE + (uint32_t)(wn * (LDH * 2)) + lane_off;
#pragma unroll
        for (int ka = 0; ka < 4; ka++) {      // 4 x k16 per stage
            uint32_t af[2][4];
#pragma unroll
            for (int ma = 0; ma < 2; ma++)
                ldmatrix_x4(af[ma], aw + (uint32_t)(ma * 16 * (LDH * 2)) + ka * 32);
            uint32_t bf[8][2];
#pragma unroll
            for (int nb = 0; nb < 4; nb++) {
                uint32_t r[4];
                ldmatrix_x4(r, bw + (uint32_t)(nb * 16 * (LDH * 2)) + ka * 32);
                bf[2 * nb][0] = r[0]; bf[2 * nb + 1][0] = r[1];
                bf[2 * nb][1] = r[2]; bf[2 * nb + 1][1] = r[3];
            }
#pragma unroll
            for (int ma = 0; ma < 2; ma++)
#pragma unroll
                for (int na = 0; na < 8; na++)
                    mma_f16(acc[ma][na], af[ma], bf[na]);
        }

        if (++p >= PIPE) p = 0;
    }

    // epilogue: tanh(acc + ws)*v, reduce over n
#pragma unroll
    for (int ma = 0; ma < 2; ma++) {
        float r0 = 0.f, r1 = 0.f;
#pragma unroll
        for (int na = 0; na < 8; na++) {
            int nl = wn + na * 8 + 2 * t;
            float w0 = sm.ws[nl], w1 = sm.ws[nl + 1];
            float v0 = sm.v[nl],  v1 = sm.v[nl + 1];
            r0 += tanh_fast(acc[ma][na][0] + w0) * v0 + tanh_fast(acc[ma][na][1] + w1) * v1;
            r1 += tanh_fast(acc[ma][na][2] + w0) * v0 + tanh_fast(acc[ma][na][3] + w1) * v1;
        }
        r0 += __shfl_xor_sync(0xffffffffu, r0, 1);
        r0 += __shfl_xor_sync(0xffffffffu, r0, 2);
        r1 += __shfl_xor_sync(0xffffffffu, r1, 1);
        r1 += __shfl_xor_sync(0xffffffffu, r1, 2);
        if (t == 0) {
            atomicAdd(&sm.rowsum[wm + ma * 16 + g], r0);
            atomicAdd(&sm.rowsum[wm + ma * 16 + g + 8], r1);
        }
    }
    __syncthreads();
    if (tid < BM) g_part[blockIdx.x][m_base + tid] = sm.rowsum[tid];
}

// ================= K2: softmax over S per batch =================
__global__ void softmax_kernel(float* __restrict__ wout) {
    __shared__ float sc[Ss];
    __shared__ float red[256];
    int b = blockIdx.x, tid = threadIdx.x;
    float mx = -1e30f;
    for (int i = tid; i < Ss; i += 256) {
        int idx = b * Ss + i;
        float v = g_part[0][idx] + g_part[1][idx] + g_part[2][idx] + g_part[3][idx];
        sc[i] = v;
        mx = fmaxf(mx, v);
    }
    red[tid] = mx; __syncthreads();
    for (int o = 128; o; o >>= 1) { if (tid < o) red[tid] = fmaxf(red[tid], red[tid + o]); __syncthreads(); }
    mx = red[0]; __syncthreads();
    float sum = 0.f;
    for (int i = tid; i < Ss; i += 256) { float e = __expf(sc[i] - mx); sc[i] = e; sum += e; }
    red[tid] = sum; __syncthreads();
    for (int o = 128; o; o >>= 1) { if (tid < o) red[tid] += red[tid + o]; __syncthreads(); }
    float inv = 1.f / red[0];
    for (int i = tid; i < Ss; i += 256) wout[b * Ss + i] = sc[i] * inv;
}

// ================= K3: context[b,h] = sum_s w[b,s] * enc[b,s,h] (fp16 enc) =================
__global__ void context_kernel(const float* __restrict__ w, float* __restrict__ out) {
    __shared__ float wsh[Ss];
    int b = blockIdx.y;
    int h2 = blockIdx.x * 256 + threadIdx.x;   // half2 column index, 0..511
    for (int i = threadIdx.x; i < Ss; i += 256) wsh[i] = w[b * Ss + i];
    __syncthreads();
    const __half2* e = reinterpret_cast<const __half2*>(g_enc_h) + (size_t)b * Ss * (Hh / 2) + h2;
    float a0 = 0.f, a1 = 0.f, b0 = 0.f, b1 = 0.f;
#pragma unroll 4
    for (int s = 0; s < Ss; s += 2) {
        float2 f0 = __half22float2(e[(size_t)s * (Hh / 2)]);
        float2 f1 = __half22float2(e[(size_t)(s + 1) * (Hh / 2)]);
        a0 += wsh[s] * f0.x;     a1 += wsh[s] * f0.y;
        b0 += wsh[s + 1] * f1.x; b1 += wsh[s + 1] * f1.y;
    }
    out[b * Hh + 2 * h2]     = a0 + b0;
    out[b * Hh + 2 * h2 + 1] = a1 + b1;
}

// ================= launcher =================
extern "C" void kernel_launch(void* const* d_in, const int* in_sizes, int n_in,
                              void* d_out, int out_size) {
    (void)in_sizes; (void)n_in; (void)out_size;
    const float* dec = (const float*)d_in[0];   // [32,1024]
    const float* enc = (const float*)d_in[1];   // [32,2048,1024]
    const float* Wh  = (const float*)d_in[2];   // [1024,1024]
    const float* Wsm = (const float*)d_in[3];   // [1024,1024]
    const float* v   = (const float*)d_in[4];   // [1024]
    float* out  = (float*)d_out;
    float* ctx  = out;                 // [32,1024]
    float* attw = out + Bb * Hh;       // [32,2048]

    cudaFuncSetAttribute(attn_scores_kernel, cudaFuncAttributeMaxDynamicSharedMemorySize,
                         (int)sizeof(SmemK1));

    wh_to_half_kernel<<<Hh * Hh / 1024, 256>>>(Wh);
    enc_to_half_kernel<<<(int)((size_t)M_TOTAL * Hh / 2048), 256>>>(enc);
    ws_kernel<<<Bb * Hh / 8, 256>>>(dec, Wsm);
    attn_scores_kernel<<<dim3(NT, M_TOTAL / BM), NTHREADS, sizeof(SmemK1)>>>(v);
    softmax_kernel<<<Bb, 256>>>(attw);
    context_kernel<<<dim3(Hh / 512, Bb), 256>>>(attw, ctx);
}

// round 7
// speedup vs baseline: 1.1434x; 1.0056x over previous
#include <cuda_runtime.h>
#include <cuda_fp16.h>
#include <cstdint>

#define DEVINL __device__ __forceinline__

// ---------------- problem sizes ----------------
constexpr int Bb = 32, Ss = 2048, Hh = 1024;
constexpr int M_TOTAL = Bb * Ss;          // 65536
constexpr int BM = 128, BN = 256, BK = 128;  // K-step = 128 elements
constexpr int NSTEPS = Hh / BK;           // 8
constexpr int NT = Hh / BN;               // 4 N-tiles
constexpr int LDH = 136;                  // padded smem row stride in halves (272B, ==16 mod 128)
constexpr int PIPE = 2;                   // ping-pong
constexpr int NTHREADS = 512;             // 16 warps

// ---------------- scratch (no allocs allowed) ----------------
__device__ float  g_ws[Bb * Hh];          // W_s @ dec
__device__ __half g_wh_h[Hh * Hh];        // fp16 W_h
__device__ __half g_enc_h[(size_t)M_TOTAL * Hh];  // fp16 encoder (128 MB)
__device__ float  g_part[NT][M_TOTAL];    // partial scores per N-tile

struct SmemK1 {
    __half A[PIPE][BM][LDH];   // 2*128*272B = 69,632 B
    __half B[PIPE][BN][LDH];   // 2*256*272B = 139,264 B
    float ws[BN];
    float v[BN];
    float rowsum[BM];
};

// ---------------- helpers ----------------
DEVINL uint32_t smem_u32(const void* p) {
    uint32_t a;
    asm("{ .reg .u64 t; cvta.to.shared.u64 t, %1; cvt.u32.u64 %0, t; }" : "=r"(a) : "l"(p));
    return a;
}
DEVINL float tanh_fast(float x) {
    float r;
    asm("tanh.approx.f32 %0, %1;" : "=f"(r) : "f"(x));
    return r;
}
DEVINL void cp_async16(uint32_t dst, const void* src) {
    asm volatile("cp.async.cg.shared.global [%0], [%1], 16;" :: "r"(dst), "l"(src));
}
DEVINL void cp_commit() { asm volatile("cp.async.commit_group;"); }
DEVINL void cp_wait0()  { asm volatile("cp.async.wait_group 0;"); }

DEVINL void ldmatrix_x4(uint32_t r[4], uint32_t addr) {
    asm volatile("ldmatrix.sync.aligned.m8n8.x4.shared.b16 {%0,%1,%2,%3}, [%4];"
                 : "=r"(r[0]), "=r"(r[1]), "=r"(r[2]), "=r"(r[3]) : "r"(addr));
}
DEVINL void mma_f16(float c[4], const uint32_t a[4], const uint32_t b[2]) {
    asm volatile(
        "mma.sync.aligned.m16n8k16.row.col.f32.f16.f16.f32 "
        "{%0,%1,%2,%3}, {%4,%5,%6,%7}, {%8,%9}, {%0,%1,%2,%3};"
        : "+f"(c[0]), "+f"(c[1]), "+f"(c[2]), "+f"(c[3])
        : "r"(a[0]), "r"(a[1]), "r"(a[2]), "r"(a[3]), "r"(b[0]), "r"(b[1]));
}
DEVINL uint32_t pack_h2(float lo, float hi) {
    __half2 h = __floats2half2_rn(lo, hi);
    return *reinterpret_cast<uint32_t*>(&h);
}

// ================= K0a: W_h -> fp16 =================
__global__ void wh_to_half_kernel(const float* __restrict__ Wh) {
    int i = (blockIdx.x * 256 + threadIdx.x) * 4;
    float4 v = *reinterpret_cast<const float4*>(Wh + i);
    uint2 u;
    u.x = pack_h2(v.x, v.y);
    u.y = pack_h2(v.z, v.w);
    *reinterpret_cast<uint2*>(g_wh_h + i) = u;
}

// ================= K0c: enc -> fp16 (8 elements/thread) =================
__global__ void enc_to_half_kernel(const float* __restrict__ enc) {
    size_t i = ((size_t)blockIdx.x * 256 + threadIdx.x) * 8;
    float4 v0 = *reinterpret_cast<const float4*>(enc + i);
    float4 v1 = *reinterpret_cast<const float4*>(enc + i + 4);
    uint4 u;
    u.x = pack_h2(v0.x, v0.y); u.y = pack_h2(v0.z, v0.w);
    u.z = pack_h2(v1.x, v1.y); u.w = pack_h2(v1.z, v1.w);
    *reinterpret_cast<uint4*>(g_enc_h + i) = u;
}

// ================= K0b: ws[b,o] = dec[b,:] . W_s[o,:] (fp32 exact) =================
__global__ void ws_kernel(const float* __restrict__ dec, const float* __restrict__ Wsm) {
    int idx = blockIdx.x * 8 + (threadIdx.x >> 5);
    int lid = threadIdx.x & 31;
    int b = idx >> 10, o = idx & 1023;
    const float* dr = dec + (size_t)b * Hh;
    const float* wr = Wsm + (size_t)o * Hh;
    float acc = 0.f;
#pragma unroll
    for (int i = 0; i < 8; i++) {
        int k = (i * 32 + lid) * 4;
        float4 d4 = *reinterpret_cast<const float4*>(dr + k);
        float4 w4 = *reinterpret_cast<const float4*>(wr + k);
        acc += d4.x * w4.x + d4.y * w4.y + d4.z * w4.z + d4.w * w4.w;
    }
#pragma unroll
    for (int off = 16; off; off >>= 1) acc += __shfl_xor_sync(0xffffffffu, acc, off);
    if (lid == 0) g_ws[idx] = acc;
}

// ================= K1: fused fp16 GEMM + tanh + v-dot -> partial scores =================
// 512 threads, warp grid 4(m) x 4(n); warp tile 32x64; BK=128, 8 steps, 1 sync/step.
__global__ __launch_bounds__(NTHREADS, 1) void attn_scores_kernel(const float* __restrict__ vvec) {
    extern __shared__ char smraw[];
    SmemK1& sm = *reinterpret_cast<SmemK1*>(smraw);

    const int tid = threadIdx.x, wid = tid >> 5, lane = tid & 31;
    const int g = lane >> 2, t = lane & 3;
    const int wm = (wid >> 2) * 32;       // 4 m-groups of 32 rows
    const int wn = (wid & 3) * 64;        // 4 n-groups of 64 cols
    const int m_base = blockIdx.y * BM;
    const int n_base = blockIdx.x * BN;
    const int b = m_base >> 11;

    for (int i = tid; i < BN; i += NTHREADS) {
        sm.ws[i] = g_ws[b * Hh + n_base + i];
        sm.v[i]  = vvec[n_base + i];
    }
    if (tid < BM) sm.rowsum[tid] = 0.f;

    // cp.async chunk coordinates: 16 chunks of 16B per 256B k-row (BK=128 halves)
    const int rA = tid >> 4, cA = tid & 15;    // rows 0..31 (+32*i), chunk col 0..15
    const __half* srcA = g_enc_h + (size_t)(m_base + rA) * Hh + cA * 8;
    const __half* srcB = g_wh_h  + (size_t)(n_base + rA) * Hh + cA * 8;

    auto issue_stage = [&](int stage, int k0) {
#pragma unroll
        for (int i = 0; i < 4; i++)   // A rows rA + 32i
            cp_async16(smem_u32(reinterpret_cast<char*>(&sm.A[stage][rA + i * 32][0]) + cA * 16),
                       srcA + (size_t)(i * 32) * Hh + k0);
#pragma unroll
        for (int i = 0; i < 8; i++)   // B rows rA + 32i
            cp_async16(smem_u32(reinterpret_cast<char*>(&sm.B[stage][rA + i * 32][0]) + cA * 16),
                       srcB + (size_t)(i * 32) * Hh + k0);
        cp_commit();
    };

    float acc[2][8][4];
#pragma unroll
    for (int ma = 0; ma < 2; ma++)
#pragma unroll
        for (int na = 0; na < 8; na++)
#pragma unroll
            for (int r = 0; r < 4; r++) acc[ma][na][r] = 0.f;

    // ldmatrix lane offset (row stride 272B == 16 mod 128 -> conflict-free)
    const int lr = lane & 7, sel = lane >> 3;
    const uint32_t lane_off = (uint32_t)((lr + (sel & 1) * 8) * (LDH * 2) + (sel >> 1) * 16);
    const uint32_t baseA = smem_u32(&sm.A[0][0][0]);
    const uint32_t baseB = smem_u32(&sm.B[0][0][0]);
    constexpr uint32_t A_STRIDE = BM * LDH * 2;   // bytes per stage
    constexpr uint32_t B_STRIDE = BN * LDH * 2;

    // prologue: stage 0
    issue_stage(0, 0);

#pragma unroll 1
    for (int s = 0; s < NSTEPS; s++) {
        int p = s & 1;
        cp_wait0();          // stage s fully loaded
        __syncthreads();     // visible to all; buffer 1-p reads (step s-1) all finished

        if (s + 1 < NSTEPS) issue_stage(1 - p, (s + 1) * BK);  // overlaps with compute below

        uint32_t aw = baseA + p * A_STRIDE + (uint32_t)(wm * (LDH * 2)) + lane_off;
        uint32_t bw = baseB + p * B_STRIDE + (uint32_t)(wn * (LDH * 2)) + lane_off;
#pragma unroll
        for (int ka = 0; ka < 8; ka++) {      // 8 x k16 per stage
            uint32_t af[2][4];
#pragma unroll
            for (int ma = 0; ma < 2; ma++)
                ldmatrix_x4(af[ma], aw + (uint32_t)(ma * 16 * (LDH * 2)) + ka * 32);
            uint32_t bf[8][2];
#pragma unroll
            for (int nb = 0; nb < 4; nb++) {
                uint32_t r[4];
                ldmatrix_x4(r, bw + (uint32_t)(nb * 16 * (LDH * 2)) + ka * 32);
                bf[2 * nb][0] = r[0]; bf[2 * nb + 1][0] = r[1];
                bf[2 * nb][1] = r[2]; bf[2 * nb + 1][1] = r[3];
            }
#pragma unroll
            for (int ma = 0; ma < 2; ma++)
#pragma unroll
                for (int na = 0; na < 8; na++)
                    mma_f16(acc[ma][na], af[ma], bf[na]);
        }
    }

    // epilogue: tanh(acc + ws)*v, reduce over n
#pragma unroll
    for (int ma = 0; ma < 2; ma++) {
        float r0 = 0.f, r1 = 0.f;
#pragma unroll
        for (int na = 0; na < 8; na++) {
            int nl = wn + na * 8 + 2 * t;
            float w0 = sm.ws[nl], w1 = sm.ws[nl + 1];
            float v0 = sm.v[nl],  v1 = sm.v[nl + 1];
            r0 += tanh_fast(acc[ma][na][0] + w0) * v0 + tanh_fast(acc[ma][na][1] + w1) * v1;
            r1 += tanh_fast(acc[ma][na][2] + w0) * v0 + tanh_fast(acc[ma][na][3] + w1) * v1;
        }
        r0 += __shfl_xor_sync(0xffffffffu, r0, 1);
        r0 += __shfl_xor_sync(0xffffffffu, r0, 2);
        r1 += __shfl_xor_sync(0xffffffffu, r1, 1);
        r1 += __shfl_xor_sync(0xffffffffu, r1, 2);
        if (t == 0) {
            atomicAdd(&sm.rowsum[wm + ma * 16 + g], r0);
            atomicAdd(&sm.rowsum[wm + ma * 16 + g + 8], r1);
        }
    }
    __syncthreads();
    if (tid < BM) g_part[blockIdx.x][m_base + tid] = sm.rowsum[tid];
}

// ================= K2: softmax over S per batch =================
__global__ void softmax_kernel(float* __restrict__ wout) {
    __shared__ float sc[Ss];
    __shared__ float red[256];
    int b = blockIdx.x, tid = threadIdx.x;
    float mx = -1e30f;
    for (int i = tid; i < Ss; i += 256) {
        int idx = b * Ss + i;
        float v = g_part[0][idx] + g_part[1][idx] + g_part[2][idx] + g_part[3][idx];
        sc[i] = v;
        mx = fmaxf(mx, v);
    }
    red[tid] = mx; __syncthreads();
    for (int o = 128; o; o >>= 1) { if (tid < o) red[tid] = fmaxf(red[tid], red[tid + o]); __syncthreads(); }
    mx = red[0]; __syncthreads();
    float sum = 0.f;
    for (int i = tid; i < Ss; i += 256) { float e = __expf(sc[i] - mx); sc[i] = e; sum += e; }
    red[tid] = sum; __syncthreads();
    for (int o = 128; o; o >>= 1) { if (tid < o) red[tid] += red[tid + o]; __syncthreads(); }
    float inv = 1.f / red[0];
    for (int i = tid; i < Ss; i += 256) wout[b * Ss + i] = sc[i] * inv;
}

// ================= K3: context[b,h] = sum_s w[b,s] * enc[b,s,h] (fp16 enc) =================
__global__ void context_kernel(const float* __restrict__ w, float* __restrict__ out) {
    __shared__ float wsh[Ss];
    int b = blockIdx.y;
    int h2 = blockIdx.x * 256 + threadIdx.x;   // half2 column index, 0..511
    for (int i = threadIdx.x; i < Ss; i += 256) wsh[i] = w[b * Ss + i];
    __syncthreads();
    const __half2* e = reinterpret_cast<const __half2*>(g_enc_h) + (size_t)b * Ss * (Hh / 2) + h2;
    float a0 = 0.f, a1 = 0.f, b0 = 0.f, b1 = 0.f;
#pragma unroll 4
    for (int s = 0; s < Ss; s += 2) {
        float2 f0 = __half22float2(e[(size_t)s * (Hh / 2)]);
        float2 f1 = __half22float2(e[(size_t)(s + 1) * (Hh / 2)]);
        a0 += wsh[s] * f0.x;     a1 += wsh[s] * f0.y;
        b0 += wsh[s + 1] * f1.x; b1 += wsh[s + 1] * f1.y;
    }
    out[b * Hh + 2 * h2]     = a0 + b0;
    out[b * Hh + 2 * h2 + 1] = a1 + b1;
}

// ================= launcher =================
extern "C" void kernel_launch(void* const* d_in, const int* in_sizes, int n_in,
                              void* d_out, int out_size) {
    (void)in_sizes; (void)n_in; (void)out_size;
    const float* dec = (const float*)d_in[0];   // [32,1024]
    const float* enc = (const float*)d_in[1];   // [32,2048,1024]
    const float* Wh  = (const float*)d_in[2];   // [1024,1024]
    const float* Wsm = (const float*)d_in[3];   // [1024,1024]
    const float* v   = (const float*)d_in[4];   // [1024]
    float* out  = (float*)d_out;
    float* ctx  = out;                 // [32,1024]
    float* attw = out + Bb * Hh;       // [32,2048]

    cudaFuncSetAttribute(attn_scores_kernel, cudaFuncAttributeMaxDynamicSharedMemorySize,
                         (int)sizeof(SmemK1));

    wh_to_half_kernel<<<Hh * Hh / 1024, 256>>>(Wh);
    enc_to_half_kernel<<<(int)((size_t)M_TOTAL * Hh / 2048), 256>>>(enc);
    ws_kernel<<<Bb * Hh / 8, 256>>>(dec, Wsm);
    attn_scores_kernel<<<dim3(NT, M_TOTAL / BM), NTHREADS, sizeof(SmemK1)>>>(v);
    softmax_kernel<<<Bb, 256>>>(attw);
    context_kernel<<<dim3(Hh / 512, Bb), 256>>>(attw, ctx);
}